// round 14
// baseline (speedup 1.0000x reference)
#include <cuda_runtime.h>
#include <cuda_bf16.h>

// ---------------- problem constants ----------------
#define NB      128
#define SEQ     77
#define DMODEL  1024
#define NHEAD   16
#define FF      4096
#define NEXP    8
#define TOPK    2
#define TOK     (NB * SEQ)          // 9856
#define QKVD    (3 * DMODEL)        // 3072
#define NPAIR   (NB * TOPK)         // 256
#define TOTROWS (NPAIR * SEQ)       // 19712
#define UROWS   (TOTROWS + TOK)     // 29568 (MoE + shared rows)
#define SHTILES (TOK / 128)         // 77
#define MAXTU   (162 + SHTILES)     // 239 unified tiles max

typedef __nv_bfloat16 bf16;

// ---------------- scratch (device globals; no allocation) ----------------
__device__ float g_xn  [(size_t)TOK * DMODEL];
__device__ float g_qkv [(size_t)TOK * QKVD];
__device__ float g_ao  [(size_t)TOK * DMODEL];
__device__ float g_x   [(size_t)TOK * DMODEL];
__device__ float g_ffn [(size_t)TOK * DMODEL];
__device__ bf16  g_ffnb[(size_t)TOK * DMODEL];
__device__ bf16  g_hmoe[(size_t)UROWS * FF];      // sorted MoE rows + shared rows
__device__ float g_eo  [(size_t)UROWS * DMODEL];  // pair-indexed MoE + shared(+x)
__device__ int   g_topi [NPAIR];
__device__ float g_gates[NPAIR];
// routing/tiling tables
__device__ int g_order[NPAIR];
__device__ int g_tileE[MAXTU];
__device__ int g_tileR[MAXTU];
__device__ int g_tileM[MAXTU];
__device__ int g_ntiles;
// transposed bf16 weights (9th slot = shared expert)
__device__ bf16 g_ew1u[(size_t)(NEXP + 1) * FF * DMODEL];
__device__ bf16 g_ew2u[(size_t)(NEXP + 1) * DMODEL * FF];
// unified biases (9th slot = shared expert)
__device__ float g_eb1u[(size_t)(NEXP + 1) * FF];
__device__ float g_eb2u[(size_t)(NEXP + 1) * DMODEL];
// tf32 pre-rounded fp32 weights
__device__ float g_pwt[(size_t)QKVD * DMODEL];
__device__ float g_owt[(size_t)DMODEL * DMODEL];

// ---------------- helpers ----------------
__device__ __forceinline__ unsigned cvt_tf32(float x) {
    unsigned r;
    asm("cvt.rna.tf32.f32 %0, %1;" : "=r"(r) : "f"(x));
    return r;
}
__device__ __forceinline__ void cp_async16(void* dst, const void* src, int sz) {
    unsigned saddr = (unsigned)__cvta_generic_to_shared(dst);
    asm volatile("cp.async.cg.shared.global [%0], [%1], 16, %2;\n"
                 :: "r"(saddr), "l"(src), "r"(sz));
}
__device__ __forceinline__ void cp_commit() {
    asm volatile("cp.async.commit_group;\n");
}
__device__ __forceinline__ void cp_wait1() {
    asm volatile("cp.async.wait_group 1;\n");
}
__device__ __forceinline__ void cp_wait2() {
    asm volatile("cp.async.wait_group 2;\n");
}
__device__ __forceinline__ void ldsm4(unsigned& r0, unsigned& r1,
                                      unsigned& r2, unsigned& r3, unsigned addr) {
    asm volatile("ldmatrix.sync.aligned.m8n8.x4.shared.b16 {%0,%1,%2,%3}, [%4];"
                 : "=r"(r0), "=r"(r1), "=r"(r2), "=r"(r3) : "r"(addr));
}

// ================= bf16 tensor-core GEMM (128x128, 256 thr, 2 CTA/SM) =====
// MODE 1: layer 1 — A rows gathered via order[] (expert<8) or direct (expert 8),
//                   C rows written sorted/direct at rowbase+i.
// MODE 2: layer 2 — A rows contiguous, C rows scattered via order[] (expert<8)
//                   or direct (rows >= TOTROWS, + resid fold).
#define AS2   72                    // smem k-pitch in bf16 (144B): ldsm conflict-free
#define TB2   (128 * AS2)           // 9216 bf16 per tile buffer
#define BGSMEM (4 * TB2 * (int)sizeof(bf16))   // 73728 B (2-stage A+B)

template<int MODE, bool RELU, bool OUTBF>
__global__ void __launch_bounds__(256, 2) bgemm(
    const bf16* __restrict__ A, const bf16* __restrict__ Bm,
    const float* __restrict__ bias, const float* __restrict__ resid,
    void* __restrict__ C, int N, int K,
    const int* __restrict__ order, const int* __restrict__ tileE,
    const int* __restrict__ tileR, const int* __restrict__ tileM,
    const int* __restrict__ ntiles)
{
    extern __shared__ bf16 sh[];

    int ty = blockIdx.y;
    if (ty >= *ntiles) return;
    int expert  = tileE[ty];
    int rowbase = tileR[ty];
    int Mloc    = tileM[ty];

    const bf16* Bp = Bm + (long)expert * N * K;
    const float* biasp = bias + (long)expert * N;

    int n0 = blockIdx.x * 128;
    int tid = threadIdx.x, lane = tid & 31, w = tid >> 5;
    int warp_m = (w & 3) * 32;
    int warp_n = (w >> 2) * 64;

    // ---- per-thread load row pointers (16B segments) ----
    int r0 = tid >> 3;              // 0..31
    int c16 = tid & 7;
    int so = c16 * 8;
    const bf16* arow[4]; int asz[4];
    const bf16* brow[4];
#pragma unroll
    for (int j = 0; j < 4; j++) {
        int i = r0 + j * 32;
        bool valid = i < Mloc;
        asz[j] = valid ? 16 : 0;
        int r = rowbase + i;
        if (MODE == 1) {
            if (expert == NEXP) {
                arow[j] = A + (long)(r - TOTROWS) * K;   // shared: direct ffnb row
            } else {
                int rc = r < TOTROWS ? r : TOTROWS - 1;
                int p = order[rc / SEQ];
                int s = rc % SEQ;
                int b = p / TOPK;
                arow[j] = A + ((long)b * SEQ + s) * K;
            }
        } else {
            arow[j] = A + (long)(valid ? r : 0) * K;
        }
        brow[j] = Bp + (long)(n0 + i) * K;
    }

    // ---- ldmatrix per-lane smem byte offsets ----
    unsigned smem_u32 = (unsigned)__cvta_generic_to_shared(sh);
    unsigned aOff[2], bOff[4];
    {
        int la = lane & 15, ha = lane >> 4;
        int nb = (lane & 7) + ((lane >> 4) & 1) * 8;
        int kb = ((lane >> 3) & 1) * 8;
#pragma unroll
        for (int mi = 0; mi < 2; mi++)
            aOff[mi] = ((warp_m + mi * 16 + la) * AS2 + ha * 8) * 2;
#pragma unroll
        for (int nj = 0; nj < 4; nj++)
            bOff[nj] = ((warp_n + nj * 16 + nb) * AS2 + kb) * 2;
    }

    float c[2][8][4];
#pragma unroll
    for (int i = 0; i < 2; i++)
#pragma unroll
        for (int j = 0; j < 8; j++)
#pragma unroll
            for (int q = 0; q < 4; q++) c[i][j][q] = 0.f;

    const int nChunks = K >> 6;

    auto loadChunk = [&](int k0, int buf) {
        bf16* Ad = sh + buf * TB2;
        bf16* Bd = sh + (2 + buf) * TB2;
#pragma unroll
        for (int j = 0; j < 4; j++) {
            int i = r0 + j * 32;
            cp_async16(Ad + i * AS2 + so, arow[j] + k0 + so, asz[j]);
            cp_async16(Bd + i * AS2 + so, brow[j] + k0 + so, 16);
        }
    };

    loadChunk(0, 0);
    cp_commit();

    for (int ch = 0; ch < nChunks; ch++) {
        if (ch + 1 < nChunks) loadChunk((ch + 1) << 6, (ch + 1) & 1);
        cp_commit();
        cp_wait1();
        __syncthreads();

        int buf = ch & 1;
        unsigned Abase = smem_u32 + buf * (TB2 * 2);
        unsigned Bbase = smem_u32 + (2 + buf) * (TB2 * 2);

#pragma unroll
        for (int kk = 0; kk < 64; kk += 16) {
            unsigned kByte = kk * 2;
            unsigned a[2][4];
#pragma unroll
            for (int mi = 0; mi < 2; mi++)
                ldsm4(a[mi][0], a[mi][1], a[mi][2], a[mi][3],
                      Abase + aOff[mi] + kByte);
#pragma unroll
            for (int nj = 0; nj < 4; nj++) {
                unsigned b0, b1, b2, b3;
                ldsm4(b0, b1, b2, b3, Bbase + bOff[nj] + kByte);
#pragma unroll
                for (int mi = 0; mi < 2; mi++) {
                    asm volatile(
                        "mma.sync.aligned.m16n8k16.row.col.f32.bf16.bf16.f32 "
                        "{%0,%1,%2,%3},{%4,%5,%6,%7},{%8,%9},{%0,%1,%2,%3};"
                        : "+f"(c[mi][nj * 2][0]), "+f"(c[mi][nj * 2][1]),
                          "+f"(c[mi][nj * 2][2]), "+f"(c[mi][nj * 2][3])
                        : "r"(a[mi][0]), "r"(a[mi][1]), "r"(a[mi][2]), "r"(a[mi][3]),
                          "r"(b0), "r"(b1));
                    asm volatile(
                        "mma.sync.aligned.m16n8k16.row.col.f32.bf16.bf16.f32 "
                        "{%0,%1,%2,%3},{%4,%5,%6,%7},{%8,%9},{%0,%1,%2,%3};"
                        : "+f"(c[mi][nj * 2 + 1][0]), "+f"(c[mi][nj * 2 + 1][1]),
                          "+f"(c[mi][nj * 2 + 1][2]), "+f"(c[mi][nj * 2 + 1][3])
                        : "r"(a[mi][0]), "r"(a[mi][1]), "r"(a[mi][2]), "r"(a[mi][3]),
                          "r"(b2), "r"(b3));
                }
            }
        }
        __syncthreads();
    }

    // -------- epilogue --------
#pragma unroll
    for (int mi = 0; mi < 2; mi++) {
#pragma unroll
        for (int half = 0; half < 2; half++) {
            int li = warp_m + mi * 16 + (lane >> 2) + half * 8;
            if (li < Mloc) {
                int r = rowbase + li;
                long ro;
                const float* rrow = nullptr;
                if (MODE == 1) {
                    ro = (long)r * N;                      // sorted / shared direct
                } else {
                    if (r >= TOTROWS) {
                        ro = (long)r * N;                  // shared region direct
                        rrow = resid + (long)(r - TOTROWS) * N;
                    } else {
                        int p = order[r / SEQ];
                        int s = r % SEQ;
                        ro = ((long)p * SEQ + s) * N;      // scatter to pair index
                    }
                }
#pragma unroll
                for (int ni = 0; ni < 8; ni++) {
                    int col = n0 + warp_n + ni * 8 + (lane & 3) * 2;
                    float v0 = c[mi][ni][half * 2 + 0];
                    float v1 = c[mi][ni][half * 2 + 1];
                    v0 += biasp[col]; v1 += biasp[col + 1];
                    if (RELU)  { v0 = fmaxf(v0, 0.f); v1 = fmaxf(v1, 0.f); }
                    if (MODE == 2 && rrow) { v0 += rrow[col]; v1 += rrow[col + 1]; }
                    if (OUTBF) {
                        __nv_bfloat162 pk = __float22bfloat162_rn(make_float2(v0, v1));
                        *(__nv_bfloat162*)((bf16*)C + ro + col) = pk;
                    } else {
                        *(float2*)((float*)C + ro + col) = make_float2(v0, v1);
                    }
                }
            }
        }
    }
}

// ================= TF32 GEMM (3-stage; pre-rounded operands) ==============
#define ASTRIDE   36
#define ABUF (128 * ASTRIDE)
#define SMEM_BYTES  (6 * ABUF * 4)    // 110592 (3-stage A+B)

template<bool RELU>
__global__ void __launch_bounds__(256, 2) tgemm(
    const float* __restrict__ A, const float* __restrict__ Bm,
    const float* __restrict__ bias, const float* __restrict__ resid,
    float* __restrict__ C, int M, int N, int K)
{
    extern __shared__ float sm[];
    float* As = sm;              // 3 buffers
    float* Bs = sm + 3 * ABUF;   // 3 buffers

    int m0 = blockIdx.y * 128;
    int n0 = blockIdx.x * 128;
    int tid = threadIdx.x, lane = tid & 31, w = tid >> 5;
    int warp_m = (w & 3) * 32;
    int warp_n = (w >> 2) * 64;

    float c[2][8][4];
#pragma unroll
    for (int i = 0; i < 2; i++)
#pragma unroll
        for (int j = 0; j < 8; j++)
#pragma unroll
            for (int q = 0; q < 4; q++) c[i][j][q] = 0.f;

    const int nChunks = K >> 5;

    auto copyChunk = [&](int k0, int buf) {
        float* dstA = As + buf * ABUF;
        float* dstB = Bs + buf * ABUF;
#pragma unroll
        for (int i = 0; i < 4; i++) {
            int f = tid + i * 256;
            int row = f >> 3;
            int kq  = (f & 7) * 4;
            int gr = m0 + row;
            int sz = (gr < M) ? 16 : 0;
            cp_async16(dstA + row * ASTRIDE + kq,
                       A + (long)(gr < M ? gr : 0) * K + k0 + kq, sz);
            cp_async16(dstB + row * ASTRIDE + kq,
                       Bm + (long)(n0 + row) * K + k0 + kq, 16);
        }
    };

    copyChunk(0, 0); cp_commit();
    if (nChunks > 1) copyChunk(32, 1);
    cp_commit();

    for (int ch = 0; ch < nChunks; ch++) {
        if (ch + 2 < nChunks) copyChunk((ch + 2) << 5, (ch + 2) % 3);
        cp_commit();
        cp_wait2();
        __syncthreads();

        int buf = ch % 3;
        const unsigned* Ab = (const unsigned*)(As + buf * ABUF);
        const unsigned* Bb = (const unsigned*)(Bs + buf * ABUF);

#pragma unroll
        for (int kk = 0; kk < 32; kk += 8) {
            int kb = kk + (lane & 3);
            unsigned a[2][4];
#pragma unroll
            for (int mi = 0; mi < 2; mi++) {
                int r = warp_m + mi * 16 + (lane >> 2);
                a[mi][0] = Ab[r * ASTRIDE + kb];
                a[mi][1] = Ab[(r + 8) * ASTRIDE + kb];
                a[mi][2] = Ab[r * ASTRIDE + kb + 4];
                a[mi][3] = Ab[(r + 8) * ASTRIDE + kb + 4];
            }
#pragma unroll
            for (int ni = 0; ni < 8; ni++) {
                int n = warp_n + ni * 8 + (lane >> 2);
                unsigned b0 = Bb[n * ASTRIDE + kb];
                unsigned b1 = Bb[n * ASTRIDE + kb + 4];
#pragma unroll
                for (int mi = 0; mi < 2; mi++) {
                    asm volatile(
                        "mma.sync.aligned.m16n8k8.row.col.f32.tf32.tf32.f32 "
                        "{%0,%1,%2,%3},{%4,%5,%6,%7},{%8,%9},{%0,%1,%2,%3};"
                        : "+f"(c[mi][ni][0]), "+f"(c[mi][ni][1]),
                          "+f"(c[mi][ni][2]), "+f"(c[mi][ni][3])
                        : "r"(a[mi][0]), "r"(a[mi][1]), "r"(a[mi][2]), "r"(a[mi][3]),
                          "r"(b0), "r"(b1));
                }
            }
        }
        __syncthreads();
    }

#pragma unroll
    for (int mi = 0; mi < 2; mi++) {
#pragma unroll
        for (int half = 0; half < 2; half++) {
            int row = m0 + warp_m + mi * 16 + (lane >> 2) + half * 8;
            if (row < M) {
                long ro = (long)row * N;
#pragma unroll
                for (int ni = 0; ni < 8; ni++) {
                    int col = n0 + warp_n + ni * 8 + (lane & 3) * 2;
                    float v0 = c[mi][ni][half * 2 + 0];
                    float v1 = c[mi][ni][half * 2 + 1];
                    if (bias)  { v0 += bias[col]; v1 += bias[col + 1]; }
                    if (RELU)  { v0 = fmaxf(v0, 0.f); v1 = fmaxf(v1, 0.f); }
                    if (resid) { v0 += resid[ro + col]; v1 += resid[ro + col + 1]; }
                    *(float2*)(C + ro + col) = make_float2(v0, v1);
                }
            }
        }
    }
}

// ---------------- tf32 pre-round (fp32 -> nearest tf32, stored fp32) -------
__global__ __launch_bounds__(256) void round_tf32_kernel(
    const float* __restrict__ in, float* __restrict__ out, long n)
{
    long i = (long)blockIdx.x * 1024 + threadIdx.x * 4;
    if (i + 3 < n) {
        float4 v = *(const float4*)(in + i);
        v.x = __uint_as_float(cvt_tf32(v.x));
        v.y = __uint_as_float(cvt_tf32(v.y));
        v.z = __uint_as_float(cvt_tf32(v.z));
        v.w = __uint_as_float(cvt_tf32(v.w));
        *(float4*)(out + i) = v;
    }
}

// ---------------- bias merge: [E,N]+ [N] -> [(E+1),N] ----------------------
__global__ __launch_bounds__(256) void biasmerge_kernel(
    const float* __restrict__ eb, const float* __restrict__ sb,
    float* __restrict__ out, int n)
{
    int i = blockIdx.x * 256 + threadIdx.x;
    if (i < NEXP * n) out[i] = eb[i];
    else if (i < (NEXP + 1) * n) out[i] = sb[i - NEXP * n];
}

// ---------------- transpose + convert fp32 [R,C] -> bf16 [C,R] -------------
__global__ __launch_bounds__(256) void tconv_kernel(
    const float* __restrict__ in, bf16* __restrict__ out, int R, int C)
{
    __shared__ float tile[32][33];
    long zoff = (long)blockIdx.z * R * C;
    in += zoff; out += zoff;
    int tx = threadIdx.x & 31, ty = threadIdx.x >> 5;
    int c0 = blockIdx.x * 32, r0 = blockIdx.y * 32;
#pragma unroll
    for (int j = 0; j < 4; j++)
        tile[ty + j * 8][tx] = in[(long)(r0 + ty + j * 8) * C + c0 + tx];
    __syncthreads();
#pragma unroll
    for (int j = 0; j < 4; j++)
        out[(long)(c0 + ty + j * 8) * R + r0 + tx] =
            __float2bfloat16_rn(tile[tx][ty + j * 8]);
}

// ---------------- layernorm (optional tf32-rounding / bf16 output) ---------
__global__ __launch_bounds__(256) void ln_kernel(
    const float* __restrict__ x, const float* __restrict__ w,
    const float* __restrict__ bvec, float* __restrict__ y,
    bf16* __restrict__ yb, int round32)
{
    long t = blockIdx.x;
    const float* xr = x + t * DMODEL;
    float* yr = y + t * DMODEL;
    int tid = threadIdx.x;
    float v[4];
    float s = 0.f, s2 = 0.f;
#pragma unroll
    for (int i = 0; i < 4; i++) {
        v[i] = xr[tid + i * 256];
        s += v[i]; s2 += v[i] * v[i];
    }
#pragma unroll
    for (int o = 16; o; o >>= 1) {
        s  += __shfl_xor_sync(0xffffffffu, s, o);
        s2 += __shfl_xor_sync(0xffffffffu, s2, o);
    }
    __shared__ float rs[8], rs2[8];
    if ((tid & 31) == 0) { rs[tid >> 5] = s; rs2[tid >> 5] = s2; }
    __syncthreads();
    float ts = 0.f, ts2 = 0.f;
#pragma unroll
    for (int i = 0; i < 8; i++) { ts += rs[i]; ts2 += rs2[i]; }
    float mean = ts * (1.0f / DMODEL);
    float var  = ts2 * (1.0f / DMODEL) - mean * mean;
    float inv  = rsqrtf(var + 1e-5f);
#pragma unroll
    for (int i = 0; i < 4; i++) {
        int d = tid + i * 256;
        float o = (v[i] - mean) * inv * w[d] + bvec[d];
        yr[d] = round32 ? __uint_as_float(cvt_tf32(o)) : o;
        if (yb) yb[t * DMODEL + d] = __float2bfloat16_rn(o);
    }
}

// ---------------- fused attention (one block per (b,h)) -------------------
__global__ __launch_bounds__(256) void attn_kernel(
    const float* __restrict__ qkv, float* __restrict__ ao)
{
    __shared__ float Ks[SEQ * 65];
    __shared__ float Vs[SEQ * 65];
    __shared__ float qb[8][64];
    __shared__ float pb[8][80];

    int bh = blockIdx.x;
    int b = bh >> 4, h = bh & 15;
    int tid = threadIdx.x, lane = tid & 31, wrp = tid >> 5;
    long tok0 = (long)b * SEQ;

    for (int idx = tid; idx < SEQ * 64; idx += 256) {
        int s = idx >> 6, d = idx & 63;
        long off = (tok0 + s) * QKVD + h * 64 + d;
        Ks[s * 65 + d] = qkv[off + DMODEL];
        Vs[s * 65 + d] = qkv[off + 2 * DMODEL];
    }
    __syncthreads();

    for (int s = wrp; s < SEQ; s += 8) {
        long qoff = (tok0 + s) * QKVD + h * 64;
        qb[wrp][lane]      = qkv[qoff + lane];
        qb[wrp][lane + 32] = qkv[qoff + lane + 32];
        __syncwarp();

        float e[3];
        float mx = -1e30f;
#pragma unroll
        for (int jj = 0; jj < 3; jj++) {
            int j = lane + jj * 32;
            float dot = -1e30f;
            if (j < SEQ) {
                const float* kr = Ks + j * 65;
                float a = 0.f;
#pragma unroll
                for (int d = 0; d < 64; d++) a += qb[wrp][d] * kr[d];
                dot = a * 0.125f;
            }
            e[jj] = dot;
            mx = fmaxf(mx, dot);
        }
#pragma unroll
        for (int o = 16; o; o >>= 1) mx = fmaxf(mx, __shfl_xor_sync(0xffffffffu, mx, o));

        float ssum = 0.f;
#pragma unroll
        for (int jj = 0; jj < 3; jj++) {
            int j = lane + jj * 32;
            float p = (j < SEQ) ? __expf(e[jj] - mx) : 0.f;
            e[jj] = p; ssum += p;
        }
#pragma unroll
        for (int o = 16; o; o >>= 1) ssum += __shfl_xor_sync(0xffffffffu, ssum, o);
        float inv = 1.0f / ssum;
#pragma unroll
        for (int jj = 0; jj < 3; jj++) {
            int j = lane + jj * 32;
            if (j < SEQ) pb[wrp][j] = e[jj] * inv;
        }
        __syncwarp();

        float a0 = 0.f, a1 = 0.f;
        for (int j = 0; j < SEQ; j++) {
            float p = pb[wrp][j];
            a0 += p * Vs[j * 65 + lane];
            a1 += p * Vs[j * 65 + lane + 32];
        }
        long orow = (tok0 + s) * DMODEL + h * 64;
        ao[orow + lane]      = __uint_as_float(cvt_tf32(a0));
        ao[orow + lane + 32] = __uint_as_float(cvt_tf32(a1));
        __syncwarp();
    }
}

// ---------------- router ----------------
__global__ __launch_bounds__(256) void router_kernel(
    const float* __restrict__ ffn, const float* __restrict__ rw,
    int* __restrict__ topi, float* __restrict__ gates)
{
    int b = blockIdx.x;
    const float* xr = ffn + (long)b * SEQ * DMODEL;
    int tid = threadIdx.x;
    int e = tid >> 5, lane = tid & 31;
    const float* wr = rw + e * DMODEL;
    float s = 0.f;
    for (int d = lane; d < DMODEL; d += 32) s += xr[d] * wr[d];
#pragma unroll
    for (int o = 16; o; o >>= 1) s += __shfl_xor_sync(0xffffffffu, s, o);
    __shared__ float lg[NEXP];
    if (lane == 0) lg[e] = s;
    __syncthreads();
    if (tid == 0) {
        int i0 = 0; float v0 = lg[0];
        for (int i = 1; i < NEXP; i++) if (lg[i] > v0) { v0 = lg[i]; i0 = i; }
        int i1 = -1; float v1 = -1e30f;
        for (int i = 0; i < NEXP; i++) if (i != i0 && lg[i] > v1) { v1 = lg[i]; i1 = i; }
        float e1 = __expf(v1 - v0);
        float den = 1.f + e1;
        topi[b * TOPK]     = i0;
        topi[b * TOPK + 1] = i1;
        gates[b * TOPK]     = 1.f / den;
        gates[b * TOPK + 1] = e1 / den;
    }
}

// ---------------- MoE routing setup (unified table incl. shared tiles) -----
__global__ void moe_setup(const int* __restrict__ topi,
                          int* __restrict__ order, int* __restrict__ tileE,
                          int* __restrict__ tileR, int* __restrict__ tileM,
                          int* __restrict__ ntiles)
{
    __shared__ int cnt[NEXP], off[NEXP];
    int tid = threadIdx.x;
    if (tid < NEXP) cnt[tid] = 0;
    __syncthreads();
    int e = topi[tid];
    int pos = atomicAdd(&cnt[e], 1);
    __syncthreads();
    if (tid == 0) {
        int o = 0;
        for (int i = 0; i < NEXP; i++) { off[i] = o; o += cnt[i]; }
    }
    __syncthreads();
    order[off[e] + pos] = tid;
    if (tid == 0) {
        int t = 0, rowbase = 0;
        for (int e2 = 0; e2 < NEXP; e2++) {
            int rows = cnt[e2] * SEQ;
            int done = 0;
            while (done < rows) {
                int m = rows - done; if (m > 128) m = 128;
                tileE[t] = e2; tileR[t] = rowbase + done; tileM[t] = m;
                t++; done += 128;
            }
            rowbase += rows;
        }
        for (int j = 0; j < SHTILES; j++) {
            tileE[t] = NEXP; tileR[t] = TOTROWS + j * 128; tileM[t] = 128;
            t++;
        }
        *ntiles = t;
    }
}

// ---------------- final combine (x already folded into shared rows) -------
__global__ __launch_bounds__(256) void combine_kernel(
    const float* __restrict__ eo, const float* __restrict__ gates,
    float* __restrict__ out)
{
    long t = blockIdx.x;
    int tid = threadIdx.x;
    int b = (int)(t / SEQ);
    int s = (int)(t - (long)b * SEQ);
    float g0 = gates[b * TOPK], g1 = gates[b * TOPK + 1];
    int d = tid * 4;
    long sh0 = ((long)TOTROWS + t) * DMODEL + d;
    long e0 = ((long)(b * TOPK) * SEQ + s) * DMODEL + d;
    long e1 = e0 + (long)SEQ * DMODEL;
    float4 vs = *(const float4*)(eo + sh0);
    float4 v0 = *(const float4*)(eo + e0);
    float4 v1 = *(const float4*)(eo + e1);
    float4 r;
    r.x = vs.x + g0 * v0.x + g1 * v1.x;
    r.y = vs.y + g0 * v0.y + g1 * v1.y;
    r.z = vs.z + g0 * v0.z + g1 * v1.z;
    r.w = vs.w + g0 * v0.w + g1 * v1.w;
    *(float4*)(out + t * DMODEL + d) = r;
}

// ---------------- launch ----------------
extern "C" void kernel_launch(void* const* d_in, const int* in_sizes, int n_in,
                              void* d_out, int out_size)
{
    const float* src   = (const float*)d_in[0];
    const float* pw    = (const float*)d_in[1];
    const float* pbias = (const float*)d_in[2];
    const float* ow    = (const float*)d_in[3];
    const float* ob    = (const float*)d_in[4];
    const float* ln1w  = (const float*)d_in[5];
    const float* ln1b  = (const float*)d_in[6];
    const float* ln2w  = (const float*)d_in[7];
    const float* ln2b  = (const float*)d_in[8];
    const float* rw    = (const float*)d_in[9];
    const float* ew1   = (const float*)d_in[10];
    const float* eb1   = (const float*)d_in[11];
    const float* ew2   = (const float*)d_in[12];
    const float* eb2   = (const float*)d_in[13];
    const float* sw1   = (const float*)d_in[14];
    const float* sb1   = (const float*)d_in[15];
    const float* sw2   = (const float*)d_in[16];
    const float* sb2   = (const float*)d_in[17];

    float *xn, *qkv, *ao, *x, *ffn, *eo, *gates, *pwt, *owt, *eb1u, *eb2u;
    bf16 *ffnb, *hmoe, *ew1u, *ew2u;
    int *topi, *order, *tileE, *tileR, *tileM, *ntiles;
    cudaGetSymbolAddress((void**)&xn,   g_xn);
    cudaGetSymbolAddress((void**)&qkv,  g_qkv);
    cudaGetSymbolAddress((void**)&ao,   g_ao);
    cudaGetSymbolAddress((void**)&x,    g_x);
    cudaGetSymbolAddress((void**)&ffn,  g_ffn);
    cudaGetSymbolAddress((void**)&ffnb, g_ffnb);
    cudaGetSymbolAddress((void**)&hmoe, g_hmoe);
    cudaGetSymbolAddress((void**)&eo,   g_eo);
    cudaGetSymbolAddress((void**)&topi, g_topi);
    cudaGetSymbolAddress((void**)&gates,g_gates);
    cudaGetSymbolAddress((void**)&order,g_order);
    cudaGetSymbolAddress((void**)&tileE,g_tileE);
    cudaGetSymbolAddress((void**)&tileR,g_tileR);
    cudaGetSymbolAddress((void**)&tileM,g_tileM);
    cudaGetSymbolAddress((void**)&ntiles,g_ntiles);
    cudaGetSymbolAddress((void**)&ew1u, g_ew1u);
    cudaGetSymbolAddress((void**)&ew2u, g_ew2u);
    cudaGetSymbolAddress((void**)&eb1u, g_eb1u);
    cudaGetSymbolAddress((void**)&eb2u, g_eb2u);
    cudaGetSymbolAddress((void**)&pwt,  g_pwt);
    cudaGetSymbolAddress((void**)&owt,  g_owt);

    cudaFuncSetAttribute(tgemm<false>, cudaFuncAttributeMaxDynamicSharedMemorySize, SMEM_BYTES);
    cudaFuncSetAttribute(bgemm<1, true,  true >, cudaFuncAttributeMaxDynamicSharedMemorySize, BGSMEM);
    cudaFuncSetAttribute(bgemm<2, false, false>, cudaFuncAttributeMaxDynamicSharedMemorySize, BGSMEM);

    const int mt_tok = TOK / 128;   // 77 (exact)

    // 0. weight convert/round prep (expert weights + shared into slot 8)
    tconv_kernel<<<dim3(FF / 32, DMODEL / 32, NEXP), 256>>>(ew1, ew1u, DMODEL, FF);
    tconv_kernel<<<dim3(FF / 32, DMODEL / 32, 1),    256>>>(sw1, ew1u + (size_t)NEXP * FF * DMODEL, DMODEL, FF);
    tconv_kernel<<<dim3(DMODEL / 32, FF / 32, NEXP), 256>>>(ew2, ew2u, FF, DMODEL);
    tconv_kernel<<<dim3(DMODEL / 32, FF / 32, 1),    256>>>(sw2, ew2u + (size_t)NEXP * DMODEL * FF, FF, DMODEL);
    biasmerge_kernel<<<((NEXP + 1) * FF + 255) / 256, 256>>>(eb1, sb1, eb1u, FF);
    biasmerge_kernel<<<((NEXP + 1) * DMODEL + 255) / 256, 256>>>(eb2, sb2, eb2u, DMODEL);
    round_tf32_kernel<<<(QKVD * DMODEL) / 1024, 256>>>(pw, pwt, (long)QKVD * DMODEL);
    round_tf32_kernel<<<(DMODEL * DMODEL) / 1024, 256>>>(ow, owt, (long)DMODEL * DMODEL);

    // 1. LN1 -> tf32-rounded xn
    ln_kernel<<<TOK, 256>>>(src, ln1w, ln1b, xn, nullptr, 1);
    // 2. QKV (TF32, 3-stage)
    tgemm<false><<<dim3(QKVD / 128, mt_tok, 1), 256, SMEM_BYTES>>>(
        xn, pwt, pbias, nullptr, qkv, TOK, QKVD, DMODEL);
    // 3. attention (writes tf32-rounded ao)
    attn_kernel<<<NB * NHEAD, 256>>>(qkv, ao);
    // 4. x = src + ao @ out_w^T + out_b  (TF32, 3-stage)
    tgemm<false><<<dim3(DMODEL / 128, mt_tok, 1), 256, SMEM_BYTES>>>(
        ao, owt, ob, src, x, TOK, DMODEL, DMODEL);
    // 5. LN2 -> fp32 (router) + bf16 (GEMM A)
    ln_kernel<<<TOK, 256>>>(x, ln2w, ln2b, ffn, ffnb, 0);
    // 6. router top-2 + unified routing tables
    router_kernel<<<NB, 256>>>(ffn, rw, topi, gates);
    moe_setup<<<1, 256>>>(topi, order, tileE, tileR, tileM, ntiles);
    // 7. unified layer 1: MoE (gather) + shared (direct) -> hmoe (bf16)
    bgemm<1, true, true><<<dim3(FF / 128, MAXTU), 256, BGSMEM>>>(
        ffnb, ew1u, eb1u, nullptr, hmoe, FF, DMODEL,
        order, tileE, tileR, tileM, ntiles);
    // 8. unified layer 2: contiguous A -> eo; shared rows get +x folded in
    bgemm<2, false, false><<<dim3(DMODEL / 128, MAXTU), 256, BGSMEM>>>(
        hmoe, ew2u, eb2u, x, eo, DMODEL, FF,
        order, tileE, tileR, tileM, ntiles);
    // 9. out = (x+shared) + g0*eo0 + g1*eo1
    combine_kernel<<<TOK, 256>>>(eo, gates, (float*)d_out);
}

// round 15
// speedup vs baseline: 1.0131x; 1.0131x over previous
#include <cuda_runtime.h>
#include <cuda_bf16.h>

// ---------------- problem constants ----------------
#define NB      128
#define SEQ     77
#define DMODEL  1024
#define NHEAD   16
#define FF      4096
#define NEXP    8
#define TOPK    2
#define TOK     (NB * SEQ)          // 9856
#define QKVD    (3 * DMODEL)        // 3072
#define NPAIR   (NB * TOPK)         // 256
#define TOTROWS (NPAIR * SEQ)       // 19712
#define UROWS   (TOTROWS + TOK)     // 29568 (MoE + shared rows)
#define SHTILES (TOK / 128)         // 77
#define MAXTU   (162 + SHTILES)     // 239 unified tiles max

typedef __nv_bfloat16 bf16;

// ---------------- scratch (device globals; no allocation) ----------------
__device__ float g_xn  [(size_t)TOK * DMODEL];
__device__ float g_qkv [(size_t)TOK * QKVD];
__device__ float g_ao  [(size_t)TOK * DMODEL];
__device__ float g_x   [(size_t)TOK * DMODEL];
__device__ float g_ffn [(size_t)TOK * DMODEL];
__device__ bf16  g_ffnb[(size_t)TOK * DMODEL];
__device__ bf16  g_hmoe[(size_t)UROWS * FF];      // sorted MoE rows + shared rows
__device__ float g_eo  [(size_t)UROWS * DMODEL];  // pair-indexed MoE + shared
__device__ int   g_topi [NPAIR];
__device__ float g_gates[NPAIR];
// routing/tiling tables
__device__ int g_order[NPAIR];
__device__ int g_tileE[MAXTU];
__device__ int g_tileR[MAXTU];
__device__ int g_tileM[MAXTU];
__device__ int g_ntiles;
// transposed bf16 weights (9th slot = shared expert)
__device__ bf16 g_ew1u[(size_t)(NEXP + 1) * FF * DMODEL];
__device__ bf16 g_ew2u[(size_t)(NEXP + 1) * DMODEL * FF];
// unified biases (9th slot = shared expert)
__device__ float g_eb1u[(size_t)(NEXP + 1) * FF];
__device__ float g_eb2u[(size_t)(NEXP + 1) * DMODEL];
// tf32 pre-rounded fp32 weights
__device__ float g_pwt[(size_t)QKVD * DMODEL];
__device__ float g_owt[(size_t)DMODEL * DMODEL];

// ---------------- helpers ----------------
__device__ __forceinline__ unsigned cvt_tf32(float x) {
    unsigned r;
    asm("cvt.rna.tf32.f32 %0, %1;" : "=r"(r) : "f"(x));
    return r;
}
__device__ __forceinline__ void cp_async16(void* dst, const void* src, int sz) {
    unsigned saddr = (unsigned)__cvta_generic_to_shared(dst);
    asm volatile("cp.async.cg.shared.global [%0], [%1], 16, %2;\n"
                 :: "r"(saddr), "l"(src), "r"(sz));
}
__device__ __forceinline__ void cp_commit() {
    asm volatile("cp.async.commit_group;\n");
}
__device__ __forceinline__ void cp_wait1() {
    asm volatile("cp.async.wait_group 1;\n");
}
__device__ __forceinline__ void cp_wait2() {
    asm volatile("cp.async.wait_group 2;\n");
}
__device__ __forceinline__ void ldsm4(unsigned& r0, unsigned& r1,
                                      unsigned& r2, unsigned& r3, unsigned addr) {
    asm volatile("ldmatrix.sync.aligned.m8n8.x4.shared.b16 {%0,%1,%2,%3}, [%4];"
                 : "=r"(r0), "=r"(r1), "=r"(r2), "=r"(r3) : "r"(addr));
}

// ================= bf16 tensor-core GEMM (128x128, 256 thr, 3-stage) ======
// MODE 1: layer 1 — A rows gathered via order[] (expert<8) or direct (expert 8),
//                   C rows written sorted/direct at rowbase+i.
// MODE 2: layer 2 — A rows contiguous, C rows scattered via order[] (expert<8)
//                   or direct (rows >= TOTROWS).
#define AS2   72                    // smem k-pitch in bf16 (144B): ldsm conflict-free
#define TB2   (128 * AS2)           // 9216 bf16 per tile buffer
#define BGSMEM (6 * TB2 * (int)sizeof(bf16))   // 110592 B (3-stage A+B)

template<int MODE, bool RELU, bool OUTBF>
__global__ void __launch_bounds__(256, 2) bgemm(
    const bf16* __restrict__ A, const bf16* __restrict__ Bm,
    const float* __restrict__ bias, void* __restrict__ C,
    int N, int K,
    const int* __restrict__ order, const int* __restrict__ tileE,
    const int* __restrict__ tileR, const int* __restrict__ tileM,
    const int* __restrict__ ntiles)
{
    extern __shared__ bf16 sh[];

    int ty = blockIdx.y;
    if (ty >= *ntiles) return;
    int expert  = tileE[ty];
    int rowbase = tileR[ty];
    int Mloc    = tileM[ty];

    const bf16* Bp = Bm + (long)expert * N * K;
    const float* biasp = bias + (long)expert * N;

    int n0 = blockIdx.x * 128;
    int tid = threadIdx.x, lane = tid & 31, w = tid >> 5;
    int warp_m = (w & 3) * 32;
    int warp_n = (w >> 2) * 64;

    // ---- per-thread load row pointers (16B segments) ----
    int r0 = tid >> 3;              // 0..31
    int c16 = tid & 7;
    int so = c16 * 8;
    const bf16* arow[4]; int asz[4];
    const bf16* brow[4];
#pragma unroll
    for (int j = 0; j < 4; j++) {
        int i = r0 + j * 32;
        bool valid = i < Mloc;
        asz[j] = valid ? 16 : 0;
        int r = rowbase + i;
        if (MODE == 1) {
            if (expert == NEXP) {
                arow[j] = A + (long)(r - TOTROWS) * K;   // shared: direct ffnb row
            } else {
                int rc = r < TOTROWS ? r : TOTROWS - 1;
                int p = order[rc / SEQ];
                int s = rc % SEQ;
                int b = p / TOPK;
                arow[j] = A + ((long)b * SEQ + s) * K;
            }
        } else {
            arow[j] = A + (long)(valid ? r : 0) * K;
        }
        brow[j] = Bp + (long)(n0 + i) * K;
    }

    // ---- ldmatrix per-lane smem byte offsets ----
    unsigned smem_u32 = (unsigned)__cvta_generic_to_shared(sh);
    unsigned aOff[2], bOff[4];
    {
        int la = lane & 15, ha = lane >> 4;
        int nb = (lane & 7) + ((lane >> 4) & 1) * 8;
        int kb = ((lane >> 3) & 1) * 8;
#pragma unroll
        for (int mi = 0; mi < 2; mi++)
            aOff[mi] = ((warp_m + mi * 16 + la) * AS2 + ha * 8) * 2;
#pragma unroll
        for (int nj = 0; nj < 4; nj++)
            bOff[nj] = ((warp_n + nj * 16 + nb) * AS2 + kb) * 2;
    }

    float c[2][8][4];
#pragma unroll
    for (int i = 0; i < 2; i++)
#pragma unroll
        for (int j = 0; j < 8; j++)
#pragma unroll
            for (int q = 0; q < 4; q++) c[i][j][q] = 0.f;

    const int nChunks = K >> 6;

    auto loadChunk = [&](int k0, int buf) {
        bf16* Ad = sh + buf * TB2;
        bf16* Bd = sh + (3 + buf) * TB2;
#pragma unroll
        for (int j = 0; j < 4; j++) {
            int i = r0 + j * 32;
            cp_async16(Ad + i * AS2 + so, arow[j] + k0 + so, asz[j]);
            cp_async16(Bd + i * AS2 + so, brow[j] + k0 + so, 16);
        }
    };

    loadChunk(0, 0); cp_commit();
    if (nChunks > 1) loadChunk(64, 1);
    cp_commit();

    for (int ch = 0; ch < nChunks; ch++) {
        if (ch + 2 < nChunks) loadChunk((ch + 2) << 6, (ch + 2) % 3);
        cp_commit();
        cp_wait2();
        __syncthreads();

        int buf = ch % 3;
        unsigned Abase = smem_u32 + buf * (TB2 * 2);
        unsigned Bbase = smem_u32 + (3 + buf) * (TB2 * 2);

#pragma unroll
        for (int kk = 0; kk < 64; kk += 16) {
            unsigned kByte = kk * 2;
            unsigned a[2][4];
#pragma unroll
            for (int mi = 0; mi < 2; mi++)
                ldsm4(a[mi][0], a[mi][1], a[mi][2], a[mi][3],
                      Abase + aOff[mi] + kByte);
#pragma unroll
            for (int nj = 0; nj < 4; nj++) {
                unsigned b0, b1, b2, b3;
                ldsm4(b0, b1, b2, b3, Bbase + bOff[nj] + kByte);
#pragma unroll
                for (int mi = 0; mi < 2; mi++) {
                    asm volatile(
                        "mma.sync.aligned.m16n8k16.row.col.f32.bf16.bf16.f32 "
                        "{%0,%1,%2,%3},{%4,%5,%6,%7},{%8,%9},{%0,%1,%2,%3};"
                        : "+f"(c[mi][nj * 2][0]), "+f"(c[mi][nj * 2][1]),
                          "+f"(c[mi][nj * 2][2]), "+f"(c[mi][nj * 2][3])
                        : "r"(a[mi][0]), "r"(a[mi][1]), "r"(a[mi][2]), "r"(a[mi][3]),
                          "r"(b0), "r"(b1));
                    asm volatile(
                        "mma.sync.aligned.m16n8k16.row.col.f32.bf16.bf16.f32 "
                        "{%0,%1,%2,%3},{%4,%5,%6,%7},{%8,%9},{%0,%1,%2,%3};"
                        : "+f"(c[mi][nj * 2 + 1][0]), "+f"(c[mi][nj * 2 + 1][1]),
                          "+f"(c[mi][nj * 2 + 1][2]), "+f"(c[mi][nj * 2 + 1][3])
                        : "r"(a[mi][0]), "r"(a[mi][1]), "r"(a[mi][2]), "r"(a[mi][3]),
                          "r"(b2), "r"(b3));
                }
            }
        }
        __syncthreads();
    }

    // -------- epilogue --------
#pragma unroll
    for (int mi = 0; mi < 2; mi++) {
#pragma unroll
        for (int half = 0; half < 2; half++) {
            int li = warp_m + mi * 16 + (lane >> 2) + half * 8;
            if (li < Mloc) {
                int r = rowbase + li;
                long ro;
                if (MODE == 1) {
                    ro = (long)r * N;                      // sorted / shared direct
                } else {
                    if (r >= TOTROWS) {
                        ro = (long)r * N;                  // shared region direct
                    } else {
                        int p = order[r / SEQ];
                        int s = r % SEQ;
                        ro = ((long)p * SEQ + s) * N;      // scatter to pair index
                    }
                }
#pragma unroll
                for (int ni = 0; ni < 8; ni++) {
                    int col = n0 + warp_n + ni * 8 + (lane & 3) * 2;
                    float v0 = c[mi][ni][half * 2 + 0];
                    float v1 = c[mi][ni][half * 2 + 1];
                    v0 += biasp[col]; v1 += biasp[col + 1];
                    if (RELU)  { v0 = fmaxf(v0, 0.f); v1 = fmaxf(v1, 0.f); }
                    if (OUTBF) {
                        __nv_bfloat162 pk = __float22bfloat162_rn(make_float2(v0, v1));
                        *(__nv_bfloat162*)((bf16*)C + ro + col) = pk;
                    } else {
                        *(float2*)((float*)C + ro + col) = make_float2(v0, v1);
                    }
                }
            }
        }
    }
}

// ================= TF32 GEMM (2-stage; pre-rounded operands) ==============
#define ASTRIDE   36
#define ABUF (128 * ASTRIDE)
#define SMEM_BYTES  (4 * ABUF * 4)    // 73728

template<bool RELU>
__global__ void __launch_bounds__(256, 2) tgemm(
    const float* __restrict__ A, const float* __restrict__ Bm,
    const float* __restrict__ bias, const float* __restrict__ resid,
    float* __restrict__ C, int M, int N, int K)
{
    extern __shared__ float sm[];
    float* As = sm;
    float* Bs = sm + 2 * ABUF;

    int m0 = blockIdx.y * 128;
    int n0 = blockIdx.x * 128;
    int tid = threadIdx.x, lane = tid & 31, w = tid >> 5;
    int warp_m = (w & 3) * 32;
    int warp_n = (w >> 2) * 64;

    float c[2][8][4];
#pragma unroll
    for (int i = 0; i < 2; i++)
#pragma unroll
        for (int j = 0; j < 8; j++)
#pragma unroll
            for (int q = 0; q < 4; q++) c[i][j][q] = 0.f;

    const int nChunks = K >> 5;

    auto copyA = [&](int k0, int buf) {
        float* dst = As + buf * ABUF;
#pragma unroll
        for (int i = 0; i < 4; i++) {
            int f = tid + i * 256;
            int row = f >> 3;
            int kq  = (f & 7) * 4;
            int gr = m0 + row;
            int sz = (gr < M) ? 16 : 0;
            const float* src = A + (long)(gr < M ? gr : 0) * K + k0 + kq;
            cp_async16(dst + row * ASTRIDE + kq, src, sz);
        }
    };
    auto copyB = [&](int k0, int buf) {
        float* dst = Bs + buf * ABUF;
#pragma unroll
        for (int i = 0; i < 4; i++) {
            int f = tid + i * 256;
            int row = f >> 3;
            int kq  = (f & 7) * 4;
            const float* src = Bm + (long)(n0 + row) * K + k0 + kq;
            cp_async16(dst + row * ASTRIDE + kq, src, 16);
        }
    };

    copyA(0, 0); copyB(0, 0);
    cp_commit();

    for (int ch = 0; ch < nChunks; ch++) {
        if (ch + 1 < nChunks) {
            copyA((ch + 1) << 5, (ch + 1) & 1);
            copyB((ch + 1) << 5, (ch + 1) & 1);
        }
        cp_commit();
        cp_wait1();
        __syncthreads();

        const unsigned* Ab = (const unsigned*)(As + (ch & 1) * ABUF);
        const unsigned* Bb = (const unsigned*)(Bs + (ch & 1) * ABUF);

#pragma unroll
        for (int kk = 0; kk < 32; kk += 8) {
            int kb = kk + (lane & 3);
            unsigned a[2][4];
#pragma unroll
            for (int mi = 0; mi < 2; mi++) {
                int r = warp_m + mi * 16 + (lane >> 2);
                a[mi][0] = Ab[r * ASTRIDE + kb];
                a[mi][1] = Ab[(r + 8) * ASTRIDE + kb];
                a[mi][2] = Ab[r * ASTRIDE + kb + 4];
                a[mi][3] = Ab[(r + 8) * ASTRIDE + kb + 4];
            }
#pragma unroll
            for (int ni = 0; ni < 8; ni++) {
                int n = warp_n + ni * 8 + (lane >> 2);
                unsigned b0 = Bb[n * ASTRIDE + kb];
                unsigned b1 = Bb[n * ASTRIDE + kb + 4];
#pragma unroll
                for (int mi = 0; mi < 2; mi++) {
                    asm volatile(
                        "mma.sync.aligned.m16n8k8.row.col.f32.tf32.tf32.f32 "
                        "{%0,%1,%2,%3},{%4,%5,%6,%7},{%8,%9},{%0,%1,%2,%3};"
                        : "+f"(c[mi][ni][0]), "+f"(c[mi][ni][1]),
                          "+f"(c[mi][ni][2]), "+f"(c[mi][ni][3])
                        : "r"(a[mi][0]), "r"(a[mi][1]), "r"(a[mi][2]), "r"(a[mi][3]),
                          "r"(b0), "r"(b1));
                }
            }
        }
        __syncthreads();
    }

#pragma unroll
    for (int mi = 0; mi < 2; mi++) {
#pragma unroll
        for (int half = 0; half < 2; half++) {
            int row = m0 + warp_m + mi * 16 + (lane >> 2) + half * 8;
            if (row < M) {
                long ro = (long)row * N;
#pragma unroll
                for (int ni = 0; ni < 8; ni++) {
                    int col = n0 + warp_n + ni * 8 + (lane & 3) * 2;
                    float v0 = c[mi][ni][half * 2 + 0];
                    float v1 = c[mi][ni][half * 2 + 1];
                    if (bias)  { v0 += bias[col]; v1 += bias[col + 1]; }
                    if (RELU)  { v0 = fmaxf(v0, 0.f); v1 = fmaxf(v1, 0.f); }
                    if (resid) { v0 += resid[ro + col]; v1 += resid[ro + col + 1]; }
                    *(float2*)(C + ro + col) = make_float2(v0, v1);
                }
            }
        }
    }
}

// ---------------- tf32 pre-round (fp32 -> nearest tf32, stored fp32) -------
__global__ __launch_bounds__(256) void round_tf32_kernel(
    const float* __restrict__ in, float* __restrict__ out, long n)
{
    long i = (long)blockIdx.x * 1024 + threadIdx.x * 4;
    if (i + 3 < n) {
        float4 v = *(const float4*)(in + i);
        v.x = __uint_as_float(cvt_tf32(v.x));
        v.y = __uint_as_float(cvt_tf32(v.y));
        v.z = __uint_as_float(cvt_tf32(v.z));
        v.w = __uint_as_float(cvt_tf32(v.w));
        *(float4*)(out + i) = v;
    }
}

// ---------------- bias merge: [E,N]+ [N] -> [(E+1),N] ----------------------
__global__ __launch_bounds__(256) void biasmerge_kernel(
    const float* __restrict__ eb, const float* __restrict__ sb,
    float* __restrict__ out, int n)
{
    int i = blockIdx.x * 256 + threadIdx.x;
    if (i < NEXP * n) out[i] = eb[i];
    else if (i < (NEXP + 1) * n) out[i] = sb[i - NEXP * n];
}

// ---------------- transpose + convert fp32 [R,C] -> bf16 [C,R] -------------
__global__ __launch_bounds__(256) void tconv_kernel(
    const float* __restrict__ in, bf16* __restrict__ out, int R, int C)
{
    __shared__ float tile[32][33];
    long zoff = (long)blockIdx.z * R * C;
    in += zoff; out += zoff;
    int tx = threadIdx.x & 31, ty = threadIdx.x >> 5;
    int c0 = blockIdx.x * 32, r0 = blockIdx.y * 32;
#pragma unroll
    for (int j = 0; j < 4; j++)
        tile[ty + j * 8][tx] = in[(long)(r0 + ty + j * 8) * C + c0 + tx];
    __syncthreads();
#pragma unroll
    for (int j = 0; j < 4; j++)
        out[(long)(c0 + ty + j * 8) * R + r0 + tx] =
            __float2bfloat16_rn(tile[tx][ty + j * 8]);
}

// ---------------- layernorm (optional tf32-rounding / bf16 output) ---------
__global__ __launch_bounds__(256) void ln_kernel(
    const float* __restrict__ x, const float* __restrict__ w,
    const float* __restrict__ bvec, float* __restrict__ y,
    bf16* __restrict__ yb, int round32)
{
    long t = blockIdx.x;
    const float* xr = x + t * DMODEL;
    float* yr = y + t * DMODEL;
    int tid = threadIdx.x;
    float v[4];
    float s = 0.f, s2 = 0.f;
#pragma unroll
    for (int i = 0; i < 4; i++) {
        v[i] = xr[tid + i * 256];
        s += v[i]; s2 += v[i] * v[i];
    }
#pragma unroll
    for (int o = 16; o; o >>= 1) {
        s  += __shfl_xor_sync(0xffffffffu, s, o);
        s2 += __shfl_xor_sync(0xffffffffu, s2, o);
    }
    __shared__ float rs[8], rs2[8];
    if ((tid & 31) == 0) { rs[tid >> 5] = s; rs2[tid >> 5] = s2; }
    __syncthreads();
    float ts = 0.f, ts2 = 0.f;
#pragma unroll
    for (int i = 0; i < 8; i++) { ts += rs[i]; ts2 += rs2[i]; }
    float mean = ts * (1.0f / DMODEL);
    float var  = ts2 * (1.0f / DMODEL) - mean * mean;
    float inv  = rsqrtf(var + 1e-5f);
#pragma unroll
    for (int i = 0; i < 4; i++) {
        int d = tid + i * 256;
        float o = (v[i] - mean) * inv * w[d] + bvec[d];
        yr[d] = round32 ? __uint_as_float(cvt_tf32(o)) : o;
        if (yb) yb[t * DMODEL + d] = __float2bfloat16_rn(o);
    }
}

// ---------------- fused attention (one block per (b,h)) -------------------
__global__ __launch_bounds__(256) void attn_kernel(
    const float* __restrict__ qkv, float* __restrict__ ao)
{
    __shared__ float Ks[SEQ * 65];
    __shared__ float Vs[SEQ * 65];
    __shared__ float qb[8][64];
    __shared__ float pb[8][80];

    int bh = blockIdx.x;
    int b = bh >> 4, h = bh & 15;
    int tid = threadIdx.x, lane = tid & 31, wrp = tid >> 5;
    long tok0 = (long)b * SEQ;

    for (int idx = tid; idx < SEQ * 64; idx += 256) {
        int s = idx >> 6, d = idx & 63;
        long off = (tok0 + s) * QKVD + h * 64 + d;
        Ks[s * 65 + d] = qkv[off + DMODEL];
        Vs[s * 65 + d] = qkv[off + 2 * DMODEL];
    }
    __syncthreads();

    for (int s = wrp; s < SEQ; s += 8) {
        long qoff = (tok0 + s) * QKVD + h * 64;
        qb[wrp][lane]      = qkv[qoff + lane];
        qb[wrp][lane + 32] = qkv[qoff + lane + 32];
        __syncwarp();

        float e[3];
        float mx = -1e30f;
#pragma unroll
        for (int jj = 0; jj < 3; jj++) {
            int j = lane + jj * 32;
            float dot = -1e30f;
            if (j < SEQ) {
                const float* kr = Ks + j * 65;
                float a = 0.f;
#pragma unroll
                for (int d = 0; d < 64; d++) a += qb[wrp][d] * kr[d];
                dot = a * 0.125f;
            }
            e[jj] = dot;
            mx = fmaxf(mx, dot);
        }
#pragma unroll
        for (int o = 16; o; o >>= 1) mx = fmaxf(mx, __shfl_xor_sync(0xffffffffu, mx, o));

        float ssum = 0.f;
#pragma unroll
        for (int jj = 0; jj < 3; jj++) {
            int j = lane + jj * 32;
            float p = (j < SEQ) ? __expf(e[jj] - mx) : 0.f;
            e[jj] = p; ssum += p;
        }
#pragma unroll
        for (int o = 16; o; o >>= 1) ssum += __shfl_xor_sync(0xffffffffu, ssum, o);
        float inv = 1.0f / ssum;
#pragma unroll
        for (int jj = 0; jj < 3; jj++) {
            int j = lane + jj * 32;
            if (j < SEQ) pb[wrp][j] = e[jj] * inv;
        }
        __syncwarp();

        float a0 = 0.f, a1 = 0.f;
        for (int j = 0; j < SEQ; j++) {
            float p = pb[wrp][j];
            a0 += p * Vs[j * 65 + lane];
            a1 += p * Vs[j * 65 + lane + 32];
        }
        long orow = (tok0 + s) * DMODEL + h * 64;
        ao[orow + lane]      = __uint_as_float(cvt_tf32(a0));
        ao[orow + lane + 32] = __uint_as_float(cvt_tf32(a1));
        __syncwarp();
    }
}

// ---------------- router ----------------
__global__ __launch_bounds__(256) void router_kernel(
    const float* __restrict__ ffn, const float* __restrict__ rw,
    int* __restrict__ topi, float* __restrict__ gates)
{
    int b = blockIdx.x;
    const float* xr = ffn + (long)b * SEQ * DMODEL;
    int tid = threadIdx.x;
    int e = tid >> 5, lane = tid & 31;
    const float* wr = rw + e * DMODEL;
    float s = 0.f;
    for (int d = lane; d < DMODEL; d += 32) s += xr[d] * wr[d];
#pragma unroll
    for (int o = 16; o; o >>= 1) s += __shfl_xor_sync(0xffffffffu, s, o);
    __shared__ float lg[NEXP];
    if (lane == 0) lg[e] = s;
    __syncthreads();
    if (tid == 0) {
        int i0 = 0; float v0 = lg[0];
        for (int i = 1; i < NEXP; i++) if (lg[i] > v0) { v0 = lg[i]; i0 = i; }
        int i1 = -1; float v1 = -1e30f;
        for (int i = 0; i < NEXP; i++) if (i != i0 && lg[i] > v1) { v1 = lg[i]; i1 = i; }
        float e1 = __expf(v1 - v0);
        float den = 1.f + e1;
        topi[b * TOPK]     = i0;
        topi[b * TOPK + 1] = i1;
        gates[b * TOPK]     = 1.f / den;
        gates[b * TOPK + 1] = e1 / den;
    }
}

// ---------------- MoE routing setup (unified table incl. shared tiles) -----
__global__ void moe_setup(const int* __restrict__ topi,
                          int* __restrict__ order, int* __restrict__ tileE,
                          int* __restrict__ tileR, int* __restrict__ tileM,
                          int* __restrict__ ntiles)
{
    __shared__ int cnt[NEXP], off[NEXP];
    int tid = threadIdx.x;
    if (tid < NEXP) cnt[tid] = 0;
    __syncthreads();
    int e = topi[tid];
    int pos = atomicAdd(&cnt[e], 1);
    __syncthreads();
    if (tid == 0) {
        int o = 0;
        for (int i = 0; i < NEXP; i++) { off[i] = o; o += cnt[i]; }
    }
    __syncthreads();
    order[off[e] + pos] = tid;
    if (tid == 0) {
        int t = 0, rowbase = 0;
        for (int e2 = 0; e2 < NEXP; e2++) {
            int rows = cnt[e2] * SEQ;
            int done = 0;
            while (done < rows) {
                int m = rows - done; if (m > 128) m = 128;
                tileE[t] = e2; tileR[t] = rowbase + done; tileM[t] = m;
                t++; done += 128;
            }
            rowbase += rows;
        }
        for (int j = 0; j < SHTILES; j++) {
            tileE[t] = NEXP; tileR[t] = TOTROWS + j * 128; tileM[t] = 128;
            t++;
        }
        *ntiles = t;
    }
}

// ---------------- final combine (vectorized) ------------------------------
__global__ __launch_bounds__(256) void combine_kernel(
    const float* __restrict__ x, const float* __restrict__ eo,
    const float* __restrict__ gates, float* __restrict__ out)
{
    long t = blockIdx.x;
    int tid = threadIdx.x;
    int b = (int)(t / SEQ);
    int s = (int)(t - (long)b * SEQ);
    float g0 = gates[b * TOPK], g1 = gates[b * TOPK + 1];
    int d = tid * 4;
    long base = t * DMODEL + d;
    long sh0 = ((long)TOTROWS + t) * DMODEL + d;
    long e0 = ((long)(b * TOPK) * SEQ + s) * DMODEL + d;
    long e1 = e0 + (long)SEQ * DMODEL;
    float4 vx = *(const float4*)(x + base);
    float4 vs = *(const float4*)(eo + sh0);
    float4 v0 = *(const float4*)(eo + e0);
    float4 v1 = *(const float4*)(eo + e1);
    float4 r;
    r.x = vx.x + vs.x + g0 * v0.x + g1 * v1.x;
    r.y = vx.y + vs.y + g0 * v0.y + g1 * v1.y;
    r.z = vx.z + vs.z + g0 * v0.z + g1 * v1.z;
    r.w = vx.w + vs.w + g0 * v0.w + g1 * v1.w;
    *(float4*)(out + base) = r;
}

// ---------------- launch ----------------
extern "C" void kernel_launch(void* const* d_in, const int* in_sizes, int n_in,
                              void* d_out, int out_size)
{
    const float* src   = (const float*)d_in[0];
    const float* pw    = (const float*)d_in[1];
    const float* pbias = (const float*)d_in[2];
    const float* ow    = (const float*)d_in[3];
    const float* ob    = (const float*)d_in[4];
    const float* ln1w  = (const float*)d_in[5];
    const float* ln1b  = (const float*)d_in[6];
    const float* ln2w  = (const float*)d_in[7];
    const float* ln2b  = (const float*)d_in[8];
    const float* rw    = (const float*)d_in[9];
    const float* ew1   = (const float*)d_in[10];
    const float* eb1   = (const float*)d_in[11];
    const float* ew2   = (const float*)d_in[12];
    const float* eb2   = (const float*)d_in[13];
    const float* sw1   = (const float*)d_in[14];
    const float* sb1   = (const float*)d_in[15];
    const float* sw2   = (const float*)d_in[16];
    const float* sb2   = (const float*)d_in[17];

    float *xn, *qkv, *ao, *x, *ffn, *eo, *gates, *pwt, *owt, *eb1u, *eb2u;
    bf16 *ffnb, *hmoe, *ew1u, *ew2u;
    int *topi, *order, *tileE, *tileR, *tileM, *ntiles;
    cudaGetSymbolAddress((void**)&xn,   g_xn);
    cudaGetSymbolAddress((void**)&qkv,  g_qkv);
    cudaGetSymbolAddress((void**)&ao,   g_ao);
    cudaGetSymbolAddress((void**)&x,    g_x);
    cudaGetSymbolAddress((void**)&ffn,  g_ffn);
    cudaGetSymbolAddress((void**)&ffnb, g_ffnb);
    cudaGetSymbolAddress((void**)&hmoe, g_hmoe);
    cudaGetSymbolAddress((void**)&eo,   g_eo);
    cudaGetSymbolAddress((void**)&topi, g_topi);
    cudaGetSymbolAddress((void**)&gates,g_gates);
    cudaGetSymbolAddress((void**)&order,g_order);
    cudaGetSymbolAddress((void**)&tileE,g_tileE);
    cudaGetSymbolAddress((void**)&tileR,g_tileR);
    cudaGetSymbolAddress((void**)&tileM,g_tileM);
    cudaGetSymbolAddress((void**)&ntiles,g_ntiles);
    cudaGetSymbolAddress((void**)&ew1u, g_ew1u);
    cudaGetSymbolAddress((void**)&ew2u, g_ew2u);
    cudaGetSymbolAddress((void**)&eb1u, g_eb1u);
    cudaGetSymbolAddress((void**)&eb2u, g_eb2u);
    cudaGetSymbolAddress((void**)&pwt,  g_pwt);
    cudaGetSymbolAddress((void**)&owt,  g_owt);

    cudaFuncSetAttribute(tgemm<false>, cudaFuncAttributeMaxDynamicSharedMemorySize, SMEM_BYTES);
    cudaFuncSetAttribute(bgemm<1, true,  true >, cudaFuncAttributeMaxDynamicSharedMemorySize, BGSMEM);
    cudaFuncSetAttribute(bgemm<2, false, false>, cudaFuncAttributeMaxDynamicSharedMemorySize, BGSMEM);

    const int mt_tok = TOK / 128;   // 77 (exact)

    // 0. weight convert/round prep (expert weights + shared into slot 8)
    tconv_kernel<<<dim3(FF / 32, DMODEL / 32, NEXP), 256>>>(ew1, ew1u, DMODEL, FF);
    tconv_kernel<<<dim3(FF / 32, DMODEL / 32, 1),    256>>>(sw1, ew1u + (size_t)NEXP * FF * DMODEL, DMODEL, FF);
    tconv_kernel<<<dim3(DMODEL / 32, FF / 32, NEXP), 256>>>(ew2, ew2u, FF, DMODEL);
    tconv_kernel<<<dim3(DMODEL / 32, FF / 32, 1),    256>>>(sw2, ew2u + (size_t)NEXP * DMODEL * FF, FF, DMODEL);
    biasmerge_kernel<<<((NEXP + 1) * FF + 255) / 256, 256>>>(eb1, sb1, eb1u, FF);
    biasmerge_kernel<<<((NEXP + 1) * DMODEL + 255) / 256, 256>>>(eb2, sb2, eb2u, DMODEL);
    round_tf32_kernel<<<(QKVD * DMODEL) / 1024, 256>>>(pw, pwt, (long)QKVD * DMODEL);
    round_tf32_kernel<<<(DMODEL * DMODEL) / 1024, 256>>>(ow, owt, (long)DMODEL * DMODEL);

    // 1. LN1 -> tf32-rounded xn
    ln_kernel<<<TOK, 256>>>(src, ln1w, ln1b, xn, nullptr, 1);
    // 2. QKV (TF32)
    tgemm<false><<<dim3(QKVD / 128, mt_tok, 1), 256, SMEM_BYTES>>>(
        xn, pwt, pbias, nullptr, qkv, TOK, QKVD, DMODEL);
    // 3. attention (writes tf32-rounded ao)
    attn_kernel<<<NB * NHEAD, 256>>>(qkv, ao);
    // 4. x = src + ao @ out_w^T + out_b  (TF32)
    tgemm<false><<<dim3(DMODEL / 128, mt_tok, 1), 256, SMEM_BYTES>>>(
        ao, owt, ob, src, x, TOK, DMODEL, DMODEL);
    // 5. LN2 -> fp32 (router) + bf16 (GEMM A)
    ln_kernel<<<TOK, 256>>>(x, ln2w, ln2b, ffn, ffnb, 0);
    // 6. router top-2 + unified routing tables
    router_kernel<<<NB, 256>>>(ffn, rw, topi, gates);
    moe_setup<<<1, 256>>>(topi, order, tileE, tileR, tileM, ntiles);
    // 7. unified layer 1: MoE (gather) + shared (direct) -> hmoe (bf16)
    bgemm<1, true, true><<<dim3(FF / 128, MAXTU), 256, BGSMEM>>>(
        ffnb, ew1u, eb1u, hmoe, FF, DMODEL,
        order, tileE, tileR, tileM, ntiles);
    // 8. unified layer 2: contiguous A -> eo (scatter MoE / direct shared)
    bgemm<2, false, false><<<dim3(DMODEL / 128, MAXTU), 256, BGSMEM>>>(
        hmoe, ew2u, eb2u, eo, DMODEL, FF,
        order, tileE, tileR, tileM, ntiles);
    // 9. out = x + shared + g0*eo0 + g1*eo1
    combine_kernel<<<TOK, 256>>>(x, eo, gates, (float*)d_out);
}